// round 17
// baseline (speedup 1.0000x reference)
#include <cuda_runtime.h>
#include <cstdint>

// Problem constants
#define SN 256        // batch == seq_len
#define EE 1024       // embedding dim
#define HH 10         // hidden dim
#define NG 40         // 4 gates * H
#define TT 50         // tagset size
#define NP (SN*SN)    // 65536 rows (t,b)
#define VV 50257      // vocab
#define WG_STRIDE 10340  // (E+H)*H per gate

// Phase A tiling (mma.sync m16n8k8 tf32)
#define BK 32         // k chunk
#define MT 128        // rows per block
#define ATHREADS 128
#define NCH (EE/BK)   // 32 chunks
#define AST 36        // padded row stride (floats) -> conflict-free fragment loads
#define A_STAGE_F (MT*AST)   // 4608 floats
#define B_STAGE_F (NG*AST)   // 1440 floats
#define NPAD 50304    // VV padded to MT multiple
#define NUB (NPAD/MT) // 393 tiles over unique tokens

// smem layout (bytes)
#define SM_STOK 0
#define SM_A    1024
#define SM_B    (SM_A + 2*A_STAGE_F*4)      // 37888
#define SM_TOT  (SM_B + 2*B_STAGE_F*4)      // 49408

// Scratch (no allocations allowed -> device globals)
__device__ float g_ubase[(size_t)NPAD * NG];  // per-unique-token projections (+bias+theta), ~8MB (L2-resident)
__device__ float g_hx[(size_t)NP * HH];       // hx outputs of the scan
__device__ __align__(16) float g_Bt[NCH * NG * BK];  // B transposed per chunk, tf32-rounded
__device__ int g_uidx[VV];                    // token -> slot (valid only for present tokens)
__device__ int g_utok[NPAD];                  // slot -> token (padding = 0)
__device__ int g_ucnt;                        // number of unique tokens
__device__ int g_rowidx[NP];                  // position -> slot

// ---------- helpers ----------
__device__ __forceinline__ void cp16(uint32_t dst, const void* src) {
    asm volatile("cp.async.cg.shared.global [%0], [%1], 16;" :: "r"(dst), "l"(src) : "memory");
}
__device__ __forceinline__ void hmma_tf32(float* d, uint32_t a0, uint32_t a1, uint32_t a2, uint32_t a3,
                                          uint32_t b0, uint32_t b1) {
    asm volatile(
        "mma.sync.aligned.m16n8k8.row.col.f32.tf32.tf32.f32 "
        "{%0,%1,%2,%3}, {%4,%5,%6,%7}, {%8,%9}, {%0,%1,%2,%3};"
        : "+f"(d[0]), "+f"(d[1]), "+f"(d[2]), "+f"(d[3])
        : "r"(a0), "r"(a1), "r"(a2), "r"(a3), "r"(b0), "r"(b1));
}
__device__ __forceinline__ float tanhapx(float x) {
    float y;
    asm("tanh.approx.f32 %0, %1;" : "=f"(y) : "f"(x));
    return y;
}

// =========================================================================
// Dedup chain
// =========================================================================
__global__ __launch_bounds__(256) void uPrep_kernel()
{
    int v = blockIdx.x * 256 + threadIdx.x;
    if (v < NPAD) g_utok[v] = 0;
    if (v < VV)   g_uidx[v] = 0;
    if (v == 0)   g_ucnt = 0;
}
__global__ __launch_bounds__(256) void uMark_kernel(const int* __restrict__ tok)
{
    int p = blockIdx.x * 256 + threadIdx.x;   // grid covers NP
    g_uidx[tok[p]] = 1;                        // idempotent store, race-free
}
__global__ __launch_bounds__(256) void uAssign_kernel()
{
    int v = blockIdx.x * 256 + threadIdx.x;
    if (v < VV && g_uidx[v]) {
        int s = atomicAdd(&g_ucnt, 1);
        g_uidx[v] = s;
        g_utok[s] = v;
    }
}
__global__ __launch_bounds__(256) void uRow_kernel(const int* __restrict__ tok)
{
    int p = blockIdx.x * 256 + threadIdx.x;
    g_rowidx[p] = g_uidx[tok[p]];
}

// =========================================================================
// B pre-transpose + tf32 round: g_Bt[ch][n][k]
// =========================================================================
__global__ __launch_bounds__(256) void prepB_kernel(const float* __restrict__ Wg)
{
    int idx = blockIdx.x * 256 + threadIdx.x;          // 0..40959
    if (idx >= NCH * NG * BK) return;
    int ch = idx / (NG * BK);
    int r  = idx % (NG * BK);
    int n  = r / BK, k = r % BK;
    float v = Wg[(n / HH) * WG_STRIDE + (ch * BK + k) * HH + (n % HH)];
    uint32_t u;
    asm("cvt.rna.tf32.f32 %0, %1;" : "=r"(u) : "f"(v));
    g_Bt[idx] = __uint_as_float(u);
}

// =========================================================================
// Phase A: skinny GEMM over UNIQUE tokens on mma.sync tf32 (HMMA).
// 128 unique rows x 40 cols per CTA; blocks past ucnt exit early.
// =========================================================================
extern __shared__ char smem_raw[];

__global__ __launch_bounds__(ATHREADS, 4) void phaseA_kernel(
    const float* __restrict__ emb,
    const float* __restrict__ bg, const float* __restrict__ theta)
{
    const int rowbase = blockIdx.x * MT;
    const int padcnt = (g_ucnt + MT - 1) & ~(MT - 1);
    if (rowbase >= padcnt) return;

    int*   stok = (int*)(smem_raw + SM_STOK);
    float* sA   = (float*)(smem_raw + SM_A);
    float* sB   = (float*)(smem_raw + SM_B);

    const int tid = threadIdx.x;
    if (tid < MT) stok[tid] = g_utok[rowbase + tid];
    __syncthreads();

    const int wid  = tid >> 5, lane = tid & 31;
    const int g    = lane >> 2, t = lane & 3;
    const int w32  = wid * 32;

    float acc[2][5][4];
#pragma unroll
    for (int m = 0; m < 2; m++)
#pragma unroll
        for (int n = 0; n < 5; n++)
#pragma unroll
            for (int q = 0; q < 4; q++) acc[m][n][q] = 0.f;

    const uint32_t sA_base = (uint32_t)__cvta_generic_to_shared(sA);
    const uint32_t sB_base = (uint32_t)__cvta_generic_to_shared(sB);

    auto issue_chunk = [&](int ch) {
        const int s = ch & 1;
        const uint32_t abase = sA_base + (uint32_t)(s * A_STAGE_F * 4);
#pragma unroll
        for (int it = 0; it < 8; it++) {
            int idx = it * ATHREADS + tid;
            int row = idx >> 3, c = idx & 7;
            cp16(abase + (uint32_t)(row * (AST * 4) + (c << 4)),
                 emb + (size_t)stok[row] * EE + ch * BK + (c << 2));
        }
        const uint32_t bbase = sB_base + (uint32_t)(s * B_STAGE_F * 4);
        const float* bsrc = g_Bt + ch * (NG * BK);
#pragma unroll
        for (int it = 0; it < 3; it++) {
            int i = it * ATHREADS + tid;
            if (i < NG * 8) {
                int n = i >> 3, kq = i & 7;
                cp16(bbase + (uint32_t)(n * (AST * 4) + (kq << 4)), bsrc + (i << 2));
            }
        }
        asm volatile("cp.async.commit_group;" ::: "memory");
    };

    issue_chunk(0);

    for (int ch = 0; ch < NCH; ch++) {
        asm volatile("cp.async.wait_group 0;" ::: "memory");
        __syncthreads();
        if (ch + 1 < NCH) issue_chunk(ch + 1);

        const int s = ch & 1;
        const uint32_t* A = (const uint32_t*)(sA + s * A_STAGE_F);
        const uint32_t* B = (const uint32_t*)(sB + s * B_STAGE_F);
#pragma unroll
        for (int s4 = 0; s4 < 4; s4++) {
            uint32_t b0[5], b1[5];
#pragma unroll
            for (int n = 0; n < 5; n++) {
                const uint32_t* bp = B + (n * 8 + g) * AST + s4 * 8 + t;
                b0[n] = bp[0];
                b1[n] = bp[4];
            }
#pragma unroll
            for (int m = 0; m < 2; m++) {
                const uint32_t* ap = A + (w32 + m * 16 + g) * AST + s4 * 8 + t;
                uint32_t a0 = ap[0];
                uint32_t a2 = ap[4];
                uint32_t a1 = ap[8 * AST];
                uint32_t a3 = ap[8 * AST + 4];
#pragma unroll
                for (int n = 0; n < 5; n++)
                    hmma_tf32(acc[m][n], a0, a1, a2, a3, b0[n], b1[n]);
            }
        }
    }

    // epilogue: add bg + theta, store (D frag: rows g/g+8, cols 2t,2t+1)
    float cbx[5], cby[5];
#pragma unroll
    for (int n = 0; n < 5; n++) {
        int col = n * 8 + 2 * t;
        cbx[n] = bg[col] + theta[col];
        cby[n] = bg[col + 1] + theta[col + 1];
    }
#pragma unroll
    for (int m = 0; m < 2; m++) {
        int row0 = rowbase + w32 + m * 16 + g;
#pragma unroll
        for (int n = 0; n < 5; n++) {
            int col = n * 8 + 2 * t;
            *(float2*)(g_ubase + (size_t)row0 * NG + col) =
                make_float2(acc[m][n][0] + cbx[n], acc[m][n][1] + cby[n]);
            *(float2*)(g_ubase + (size_t)(row0 + 8) * NG + col) =
                make_float2(acc[m][n][2] + cbx[n], acc[m][n][3] + cby[n]);
        }
    }
}

// =========================================================================
// Phase B: one LSTM chain per warp. Rotated lane mapping (lane l = wire
// (l+1)%10), radix-4 scan, tanh.approx. Base reads indirect through
// g_rowidx into L2-resident g_ubase; rowidx fetched one 4-step block
// ahead of the base prefetch (chain fits easily in the window).
// =========================================================================
__global__ __launch_bounds__(32) void phaseB_kernel(const float* __restrict__ Wg)
{
    const int lane = threadIdx.x;
    const int grp  = lane >> 4;          // 0: f,i   1: g,o
    const int l    = lane & 15;
    const int b    = blockIdx.x;
    const bool on  = (l < HH);
    const int  w   = (l + 1) % HH;       // rotated wire index

    const int gA = grp ? 2 : 0;          // f or g
    const int gB = grp ? 3 : 1;          // i or o

    float wA[HH], wB[HH];
#pragma unroll
    for (int j = 0; j < HH; j++) {
        wA[j] = on ? Wg[gA * WG_STRIDE + (EE + j) * HH + w] : 0.f;
        wB[j] = on ? Wg[gB * WG_STRIDE + (EE + j) * HH + w] : 0.f;
    }

    // gate A activation: grp0 sigmoid -> 0.5 + 0.5*tanh(0.5x); grp1 tanh
    const float ssA = grp ? 1.f : 0.5f;
    const float kA  = grp ? 1.f : 0.5f;
    const float bAc = grp ? 0.f : 0.5f;

    float hx = 0.f, cx = 0.f;
    const int offA = gA * 10 + w;
    const int offB = gB * 10 + w;
    const int* rp = g_rowidx + b;        // stride SN per t

    int r1[4], r2[4];
    float pA[4], pB[4];
    {
        int r0[4];
#pragma unroll
        for (int i = 0; i < 4; i++) r0[i] = rp[i * SN];
#pragma unroll
        for (int i = 0; i < 4; i++) {
            pA[i] = on ? g_ubase[(size_t)r0[i] * NG + offA] : 0.f;
            pB[i] = on ? g_ubase[(size_t)r0[i] * NG + offB] : 0.f;
        }
#pragma unroll
        for (int i = 0; i < 4; i++) r1[i] = rp[(4 + i) * SN];
    }

#pragma unroll 1
    for (int t0 = 0; t0 < SN; t0 += 4) {
        float nA[4], nB[4];
        if (t0 + 4 < SN) {
#pragma unroll
            for (int i = 0; i < 4; i++) {       // batch 8 LDGs (L2-resident ubase)
                nA[i] = on ? g_ubase[(size_t)r1[i] * NG + offA] : 0.f;
                nB[i] = on ? g_ubase[(size_t)r1[i] * NG + offB] : 0.f;
            }
#pragma unroll
            for (int i = 0; i < 4; i++)
                r2[i] = (t0 + 8 < SN) ? rp[(t0 + 8 + i) * SN] : 0;
        } else {
#pragma unroll
            for (int i = 0; i < 4; i++) { nA[i] = 0.f; nB[i] = 0.f; r2[i] = 0; }
        }
#pragma unroll
        for (int tt = 0; tt < 4; tt++) {
            // broadcast hx(t-1): wire j lives at lane (j+9)%10
            float aA0 = pA[tt], aA1 = 0.f, aB0 = pB[tt], aB1 = 0.f;
#pragma unroll
            for (int j = 0; j < HH; j += 2) {
                float hj0 = __shfl_sync(0xffffffffu, hx, (j + 9) % 10, 16);  // wire j
                float hj1 = __shfl_sync(0xffffffffu, hx, j, 16);             // wire j+1
                aA0 = fmaf(hj0, wA[j], aA0);
                aA1 = fmaf(hj1, wA[j + 1], aA1);
                aB0 = fmaf(hj0, wB[j], aB0);
                aB1 = fmaf(hj1, wB[j + 1], aB1);
            }
            float aA = aA0 + aA1, aB = aB0 + aB1;

            // qlayer: cos, then radix-4 inclusive prefix scan (2 levels)
            float cA = __cosf(aA), cB = __cosf(aB);
            float dA = cA, dB = cB;
            float c0A = __shfl_sync(0xffffffffu, cA, 9, 16);
            float c0B = __shfl_sync(0xffffffffu, cB, 9, 16);
            float rcA = __fdividef(1.f, cA);
            float rcB = __fdividef(1.f, cB);
            // level 1: offsets 1,2,3
            {
                float a1 = __shfl_up_sync(0xffffffffu, dA, 1, 16);
                float a2 = __shfl_up_sync(0xffffffffu, dA, 2, 16);
                float a3 = __shfl_up_sync(0xffffffffu, dA, 3, 16);
                float b1 = __shfl_up_sync(0xffffffffu, dB, 1, 16);
                float b2 = __shfl_up_sync(0xffffffffu, dB, 2, 16);
                float b3 = __shfl_up_sync(0xffffffffu, dB, 3, 16);
                float mA = ((l >= 1) ? a1 : 1.f) * ((l >= 2) ? a2 : 1.f);
                float mB = ((l >= 1) ? b1 : 1.f) * ((l >= 2) ? b2 : 1.f);
                dA *= mA * ((l >= 3) ? a3 : 1.f);
                dB *= mB * ((l >= 3) ? b3 : 1.f);
            }
            // level 2: offsets 4,8,12
            {
                float a1 = __shfl_up_sync(0xffffffffu, dA, 4, 16);
                float a2 = __shfl_up_sync(0xffffffffu, dA, 8, 16);
                float a3 = __shfl_up_sync(0xffffffffu, dA, 12, 16);
                float b1 = __shfl_up_sync(0xffffffffu, dB, 4, 16);
                float b2 = __shfl_up_sync(0xffffffffu, dB, 8, 16);
                float b3 = __shfl_up_sync(0xffffffffu, dB, 12, 16);
                float mA = ((l >= 4) ? a1 : 1.f) * ((l >= 8) ? a2 : 1.f);
                float mB = ((l >= 4) ? b1 : 1.f) * ((l >= 8) ? b2 : 1.f);
                dA *= mA * ((l >= 12) ? a3 : 1.f);
                dB *= mB * ((l >= 12) ? b3 : 1.f);
            }
            // finals: no post-scan shuffle
            float qA = dA * ((l == 9) ? rcA : c0A);
            float qB = dB * ((l == 9) ? rcB : c0B);

            // activations via tanh.approx
            float actA = fmaf(kA, tanhapx(ssA * qA), bAc);          // f / g
            float actB = fmaf(0.5f, tanhapx(0.5f * qB), 0.5f);      // i / o

            // exchange halves: grp0 gets (g,o), grp1 gets (f,i)
            float xA = __shfl_xor_sync(0xffffffffu, actA, 16);
            float xB = __shfl_xor_sync(0xffffffffu, actB, 16);
            float f  = grp ? xA   : actA;
            float ii = grp ? xB   : actB;
            float gg = grp ? actA : xA;
            float o  = grp ? actB : xB;

            cx = fmaf(f, cx, ii * gg);
            hx = o * tanhapx(cx);

            if (on && grp == 0) g_hx[((size_t)(t0 + tt) * SN + b) * HH + w] = hx;
        }
#pragma unroll
        for (int i = 0; i < 4; i++) { pA[i] = nA[i]; pB[i] = nB[i]; r1[i] = r2[i]; }
    }
}

// =========================================================================
// Phase C: logits = hx @ W_out + b_out, then log_softmax over T=50.
// One row per thread; output staged in 16B-aligned smem, then
// block-cooperative float4 copy (coalesced stores). Measured ~11us.
// =========================================================================
__global__ __launch_bounds__(128) void phaseC_kernel(
    const float* __restrict__ Wout, const float* __restrict__ bout,
    float* __restrict__ out)
{
    __shared__ __align__(16) float sOut[128 * TT];   // 25.6 KB, 16B aligned
    __shared__ float sW[HH * TT];
    __shared__ float sbv[TT];
    const int tid = threadIdx.x;
    for (int i = tid; i < HH * TT; i += 128) sW[i] = Wout[i];
    for (int i = tid; i < TT;      i += 128) sbv[i] = bout[i];
    __syncthreads();

    const int row = blockIdx.x * 128 + tid;
    float h[HH];
#pragma unroll
    for (int j = 0; j < HH; j += 2) {
        float2 v = *(const float2*)(g_hx + (size_t)row * HH + j);
        h[j] = v.x; h[j + 1] = v.y;
    }

    float lg[TT];
#pragma unroll
    for (int c = 0; c < TT; c++) {
        float s = sbv[c];
#pragma unroll
        for (int j = 0; j < HH; j++) s = fmaf(h[j], sW[j * TT + c], s);
        lg[c] = s;
    }
    float m = lg[0];
#pragma unroll
    for (int c = 1; c < TT; c++) m = fmaxf(m, lg[c]);
    float sum = 0.f;
#pragma unroll
    for (int c = 0; c < TT; c++) sum += __expf(lg[c] - m);
    float ls = m + __logf(sum);

    float2* sp = (float2*)(sOut + tid * TT);
#pragma unroll
    for (int c = 0; c < TT / 2; c++)
        sp[c] = make_float2(lg[2 * c] - ls, lg[2 * c + 1] - ls);
    __syncthreads();

    // coalesced block copy: 128*50 floats = 1600 float4
    const float4* src = (const float4*)sOut;
    float4* dst = (float4*)(out + (size_t)blockIdx.x * 128 * TT);
#pragma unroll
    for (int i = 0; i < 13; i++) {
        int idx = i * 128 + tid;
        if (idx < (128 * TT) / 4) dst[idx] = src[idx];
    }
}

// =========================================================================
extern "C" void kernel_launch(void* const* d_in, const int* in_sizes, int n_in,
                              void* d_out, int out_size)
{
    const int*   tok   = (const int*)d_in[0];     // sentence (256,256) int32
    const float* emb   = (const float*)d_in[1];   // (V, E)
    const float* Wg    = (const float*)d_in[2];   // (4, E+H, H)
    const float* bg    = (const float*)d_in[3];   // (4, H)
    const float* theta = (const float*)d_in[4];   // (4, H)
    const float* Wout  = (const float*)d_in[5];   // (H, T)
    const float* bout  = (const float*)d_in[6];   // (T)
    float* out = (float*)d_out;                   // (256,256,50) float32

    cudaFuncSetAttribute(phaseA_kernel, cudaFuncAttributeMaxDynamicSharedMemorySize, SM_TOT);

    prepB_kernel<<<(NCH * NG * BK + 255) / 256, 256>>>(Wg);
    uPrep_kernel<<<(NPAD + 255) / 256, 256>>>();
    uMark_kernel<<<NP / 256, 256>>>(tok);
    uAssign_kernel<<<(VV + 255) / 256, 256>>>();
    uRow_kernel<<<NP / 256, 256>>>(tok);
    phaseA_kernel<<<NUB, ATHREADS, SM_TOT>>>(emb, bg, theta);
    phaseB_kernel<<<SN, 32>>>(Wg);
    phaseC_kernel<<<NP / 128, 128>>>(Wout, bout, out);
}